// round 2
// baseline (speedup 1.0000x reference)
#include <cuda_runtime.h>
#include <math.h>

// ---------------------------------------------------------------------------
// Problem constants
// ---------------------------------------------------------------------------
#define BSZ   16
#define LSEQ  50
#define NBLK  64          // num_blk_pervisit == MEM_UPDATE == MEM_SIZE
#define DM    256         // d_model
#define DH    512         // hidden (2*D)
#define KD    768         // block embedding dim
#define NTOK  (BSZ*LSEQ*NBLK)   // 51200
#define NBL   (BSZ*LSEQ)        // 800
#define SLOTS (LSEQ*NBLK)       // 3200 per batch

__device__ __forceinline__ float neg_inf() { return __int_as_float(0xff800000); }

// ---------------------------------------------------------------------------
// Scratch (static device globals; no allocation)
// ---------------------------------------------------------------------------
__device__ __align__(128) float g_H [(size_t)NTOK*DH];  // hidden / reused as tanh-activations
__device__ __align__(128) float g_Y [(size_t)NTOK*DM];  // pre-LN output
__device__ __align__(128) float g_VT[(size_t)NTOK*DM];  // v_text (post-LN)
__device__ __align__(128) float g_KV[(size_t)NTOK*DM];  // v_text @ wk
__device__ __align__(128) float g_S [NTOK];             // raw attention scores
__device__ __align__(128) float g_T [NBL*DM];           // tv @ am_w1[:D] + am_b1
__device__ __align__(128) float g_QW[NBL*DM];           // (tv+v) @ wq
__device__ int   g_selslot[NTOK];                       // per (b,l): slots in sel order
__device__ int   g_fslot[BSZ*64];                       // final memory slots
__device__ int   g_fid  [BSZ*64];                       // final memory ids
__device__ __align__(128) float g_vfin[BSZ*DM];
__device__ __align__(128) float g_mfin[BSZ*DM];

// ---------------------------------------------------------------------------
// Generic fp32 tiled GEMM: C[M,N] = act(A[M,K] @ B[K,N] + bias + rowbias)
//   - optional row gather on A (embedding lookup)
//   - accumulation order per output element is fixed (k ascending), so
//     identical gathered rows produce bitwise-identical outputs (needed for
//     exact tie-break replication of lax.top_k on duplicate ids).
// BM=BN=128, BK=16, 256 threads, 8x8 microtile.
// ---------------------------------------------------------------------------
__global__ void __launch_bounds__(256) gemm128(
    const float* __restrict__ A, const float* __restrict__ B, float* __restrict__ C,
    int Kdim, int Ndim,
    const int*  __restrict__ gather,
    const float* __restrict__ bias,      // per-n, may be null
    const float* __restrict__ rowbias,   // indexed [(m>>6)*Ndim + n], may be null
    int act)                             // 0=none 1=relu 2=tanh
{
    __shared__ __align__(16) float As[16][128];
    __shared__ __align__(16) float Bs[16][128];
    const int bm = blockIdx.x * 128, bn = blockIdx.y * 128;
    const int tid = threadIdx.x;
    const int ty = tid >> 4, tx = tid & 15;
    const int arow = tid >> 2, akc = (tid & 3) * 4;     // A: 2 rows per thread
    const int bkr  = tid >> 5, bnc = (tid & 31) * 4;    // B: 2 k-rows per thread

    int r0 = bm + arow, r1 = bm + arow + 64;
    if (gather) { r0 = gather[r0]; r1 = gather[r1]; }
    const float* Ar0 = A + (size_t)r0 * Kdim + akc;
    const float* Ar1 = A + (size_t)r1 * Kdim + akc;
    const float* Bp  = B + (size_t)bkr * Ndim + bn + bnc;

    float acc[8][8];
#pragma unroll
    for (int i = 0; i < 8; i++)
#pragma unroll
        for (int j = 0; j < 8; j++) acc[i][j] = 0.f;

    for (int k0 = 0; k0 < Kdim; k0 += 16) {
        float4 a0 = *(const float4*)(Ar0 + k0);
        float4 a1 = *(const float4*)(Ar1 + k0);
        float4 b0 = *(const float4*)(Bp + (size_t)k0 * Ndim);
        float4 b1 = *(const float4*)(Bp + (size_t)(k0 + 8) * Ndim);
        __syncthreads();
        As[akc+0][arow] = a0.x; As[akc+1][arow] = a0.y;
        As[akc+2][arow] = a0.z; As[akc+3][arow] = a0.w;
        As[akc+0][arow+64] = a1.x; As[akc+1][arow+64] = a1.y;
        As[akc+2][arow+64] = a1.z; As[akc+3][arow+64] = a1.w;
        *(float4*)&Bs[bkr  ][bnc] = b0;
        *(float4*)&Bs[bkr+8][bnc] = b1;
        __syncthreads();
#pragma unroll
        for (int kk = 0; kk < 16; kk++) {
            float4 aA = *(const float4*)&As[kk][ty*8];
            float4 aB = *(const float4*)&As[kk][ty*8+4];
            float4 bA = *(const float4*)&Bs[kk][tx*8];
            float4 bB = *(const float4*)&Bs[kk][tx*8+4];
            float av[8] = {aA.x,aA.y,aA.z,aA.w,aB.x,aB.y,aB.z,aB.w};
            float bv[8] = {bA.x,bA.y,bA.z,bA.w,bB.x,bB.y,bB.z,bB.w};
#pragma unroll
            for (int i = 0; i < 8; i++)
#pragma unroll
                for (int j = 0; j < 8; j++)
                    acc[i][j] = fmaf(av[i], bv[j], acc[i][j]);
        }
    }

#pragma unroll
    for (int i = 0; i < 8; i++) {
        int m = bm + ty*8 + i;
#pragma unroll
        for (int j = 0; j < 8; j++) {
            int n = bn + tx*8 + j;
            float v = acc[i][j];
            if (bias)    v += bias[n];
            if (rowbias) v += rowbias[(m >> 6) * Ndim + n];
            if (act == 1)      v = fmaxf(v, 0.f);
            else if (act == 2) v = tanhf(v);
            C[(size_t)m * Ndim + n] = v;
        }
    }
}

// ---------------------------------------------------------------------------
// Per-(b,l) precompute: g_T = tv @ am_w1[:D] + am_b1 ;  g_QW = (tv+v) @ wq
// ---------------------------------------------------------------------------
__global__ void prep_k(const float* __restrict__ v, const float* __restrict__ tv,
                       const float* __restrict__ am_w1, const float* __restrict__ am_b1,
                       const float* __restrict__ wq)
{
    __shared__ float tvs[DM];
    __shared__ float qs[DM];
    int bl = blockIdx.x, d = threadIdx.x;
    float t0 = tv[(size_t)bl*DM + d];
    tvs[d] = t0;
    qs[d]  = t0 + v[(size_t)bl*DM + d];
    __syncthreads();
    float t = am_b1[d], q = 0.f;
    for (int k = 0; k < DM; k++) {
        t = fmaf(tvs[k], am_w1[k*DM + d], t);
        q = fmaf(qs[k],  wq  [k*DM + d], q);
    }
    g_T [(size_t)bl*DM + d] = t;
    g_QW[(size_t)bl*DM + d] = q;
}

// ---------------------------------------------------------------------------
// LayerNorm per token row (fixed reduction tree -> deterministic per id)
// ---------------------------------------------------------------------------
__global__ void ln_k(const float* __restrict__ gamma, const float* __restrict__ beta)
{
    int tok = blockIdx.x, d = threadIdx.x;
    __shared__ float red[DM];
    __shared__ float smu, sis;
    float y = g_Y[(size_t)tok*DM + d];
    red[d] = y; __syncthreads();
    for (int s = 128; s > 0; s >>= 1) { if (d < s) red[d] += red[d+s]; __syncthreads(); }
    if (d == 0) smu = red[0] * (1.f/DM);
    __syncthreads();
    float c = y - smu;
    red[d] = c*c; __syncthreads();
    for (int s = 128; s > 0; s >>= 1) { if (d < s) red[d] += red[d+s]; __syncthreads(); }
    if (d == 0) sis = rsqrtf(red[0] * (1.f/DM) + 1e-5f);
    __syncthreads();
    g_VT[(size_t)tok*DM + d] = gamma[d]*c*sis + beta[d];
}

// ---------------------------------------------------------------------------
// score = tanh_activations . am_w2  (one warp per token; fixed shuffle tree)
// ---------------------------------------------------------------------------
__global__ void score_k(const float* __restrict__ am_w2)
{
    int tok  = blockIdx.x * 8 + (threadIdx.x >> 5);
    int lane = threadIdx.x & 31;
    const float* a = g_H + (size_t)tok * DM;   // g_H reused as tanh activations
    float s = 0.f;
#pragma unroll
    for (int k = lane; k < DM; k += 32) s = fmaf(a[k], am_w2[k], s);
    for (int o = 16; o > 0; o >>= 1) s += __shfl_down_sync(0xffffffffu, s, o);
    if (lane == 0) g_S[tok] = s;
}

// ---------------------------------------------------------------------------
// Per-visit stable sort (replicates softmax->mask->top_k(64 of 64)):
// unmasked by raw score desc (softmax monotone), masked (-inf) by index.
// Rank comparator matches lax.top_k tie-break (lower index first).
// ---------------------------------------------------------------------------
__global__ void select_k(const int* __restrict__ masks)
{
    int bl = blockIdx.x, j = threadIdx.x;
    __shared__ float key[64];
    int tok = bl*64 + j;
    float k_ = masks[tok] ? g_S[tok] : neg_inf();
    key[j] = k_; __syncthreads();
    int rank = 0;
    for (int m = 0; m < 64; m++) {
        float o = key[m];
        rank += (o > k_) || (o == k_ && m < j);
    }
    g_selslot[bl*64 + rank] = (bl % LSEQ) * NBLK + j;
}

// ---------------------------------------------------------------------------
// Sequential memory recurrence: one block per batch, 49 steps.
// Candidates carry SLOT indices into the per-batch kvec/v_text tables, so
// x@wk is a gather of precomputed rows (same id -> bitwise-same kvec -> jax
// tie-breaks reproduced exactly via index order).
// ---------------------------------------------------------------------------
__global__ void recur_k(const int* __restrict__ ids, const int* __restrict__ masks,
                        const int* __restrict__ lens)
{
    int b = blockIdx.x, tid = threadIdx.x;
    __shared__ __align__(16) float qw[DM];
    __shared__ int cslot[64], cmask[64];
    __shared__ int nslot[64], nmask[64];
    __shared__ int dslot[128], dmask[128];
    __shared__ float ev[128];

    if (tid < 64) {
        int slot = g_selslot[(b*LSEQ + 0)*64 + tid];
        cslot[tid] = slot;
        cmask[tid] = masks[b*SLOTS + slot];
    }
    int lb = lens[b];
    __syncthreads();

    for (int t = 1; t < LSEQ; t++) {
        qw[tid] = g_QW[(size_t)(b*LSEQ + t)*DM + tid];
        if (tid < 128) {
            int slot = (tid < 64) ? cslot[tid] : g_selslot[(b*LSEQ + t)*64 + (tid - 64)];
            dslot[tid] = slot;
            dmask[tid] = (tid < 64) ? cmask[tid] : masks[b*SLOTS + slot];
        }
        __syncthreads();

        int w = tid >> 5, lane = tid & 31;
        for (int c = w; c < 128; c += 8) {
            const float4* kv = (const float4*)(g_KV + ((size_t)b*SLOTS + dslot[c]) * DM);
            const float4* q4 = (const float4*)qw;
            float4 k0 = kv[lane*2], k1 = kv[lane*2 + 1];
            float4 q0 = q4[lane*2], q1 = q4[lane*2 + 1];
            float s = k0.x*q0.x + k0.y*q0.y + k0.z*q0.z + k0.w*q0.w
                    + k1.x*q1.x + k1.y*q1.y + k1.z*q1.z + k1.w*q1.w;
            for (int o = 16; o > 0; o >>= 1) s += __shfl_down_sync(0xffffffffu, s, o);
            if (lane == 0) ev[c] = s;   // scale /sqrt(D) and softmax are monotone: skip
        }
        __syncthreads();

        if (tid < 128) {
            float k_ = dmask[tid] ? ev[tid] : neg_inf();
            int rank = 0;
            for (int m = 0; m < 128; m++) {
                float o = dmask[m] ? ev[m] : neg_inf();
                rank += (o > k_) || (o == k_ && m < tid);
            }
            if (rank < 64) { nslot[rank] = dslot[tid]; nmask[rank] = dmask[tid]; }
        }
        __syncthreads();
        if (tid < 64) {
            cslot[tid] = nslot[tid];
            cmask[tid] = nmask[tid];
            if (t == lb - 1) g_fslot[b*64 + tid] = nslot[tid];  // memory[lengths-1] == ys[lengths-2]
        }
        __syncthreads();
    }
}

// ---------------------------------------------------------------------------
// Pools: length-masked max over tv; max over gathered v_text of final memory.
// ---------------------------------------------------------------------------
__global__ void final_k(const float* __restrict__ tv, const int* __restrict__ ids,
                        const int* __restrict__ lens)
{
    int b = blockIdx.x, d = threadIdx.x;
    int lb = lens[b];
    float mx = neg_inf();
    for (int l = 0; l < lb; l++) mx = fmaxf(mx, tv[((size_t)b*LSEQ + l)*DM + d]);
    g_vfin[b*DM + d] = mx;
    float mv = neg_inf();
    for (int m = 0; m < 64; m++) {
        int slot = g_fslot[b*64 + m];
        mv = fmaxf(mv, g_VT[((size_t)b*SLOTS + slot)*DM + d]);
    }
    g_mfin[b*DM + d] = mv;
    if (d < 64) g_fid[b*64 + d] = ids[b*SLOTS + g_fslot[b*64 + d]];
}

// ---------------------------------------------------------------------------
// Output head + flatten (output[16,2] then memory_final[16,64] as float32)
// ---------------------------------------------------------------------------
__global__ void out_k(const float* __restrict__ ow, const float* __restrict__ ob,
                      float* __restrict__ out, int out_size)
{
    int tid = threadIdx.x;
    if (tid < 32) {
        int b = tid >> 1, o = tid & 1;
        float v = ob[o];
        for (int d = 0; d < DM; d++) v = fmaf(g_vfin[b*DM + d], ow[d*2 + o], v);
        for (int d = 0; d < DM; d++) v = fmaf(g_mfin[b*DM + d], ow[(DM + d)*2 + o], v);
        if (tid < out_size) out[tid] = v;
    }
    for (int i = tid; i < BSZ*64; i += blockDim.x)
        if (32 + i < out_size) out[32 + i] = (float)g_fid[i];
    for (int i = 32 + BSZ*64 + tid; i < out_size; i += blockDim.x)
        out[i] = 0.f;
}

// ---------------------------------------------------------------------------
// Launch
// ---------------------------------------------------------------------------
extern "C" void kernel_launch(void* const* d_in, const int* in_sizes, int n_in,
                              void* d_out, int out_size)
{
    const float* v_all  = (const float*)d_in[0];
    const float* tv_all = (const float*)d_in[1];
    const float* emb    = (const float*)d_in[2];
    const float* w1     = (const float*)d_in[3];
    const float* b1     = (const float*)d_in[4];
    const float* w2     = (const float*)d_in[5];
    const float* b2     = (const float*)d_in[6];
    const float* gam    = (const float*)d_in[7];
    const float* bet    = (const float*)d_in[8];
    const float* wq     = (const float*)d_in[9];
    const float* wk     = (const float*)d_in[10];
    const float* amw1   = (const float*)d_in[11];
    const float* amb1   = (const float*)d_in[12];
    const float* amw2   = (const float*)d_in[13];
    const float* ow     = (const float*)d_in[14];
    const float* ob     = (const float*)d_in[15];
    const int*   itxt   = (const int*)d_in[16];
    const int*   mtxt   = (const int*)d_in[17];
    const int*   lens   = (const int*)d_in[18];
    float* out = (float*)d_out;

    float *pH, *pY, *pVT, *pKV, *pT;
    cudaGetSymbolAddress((void**)&pH,  g_H);
    cudaGetSymbolAddress((void**)&pY,  g_Y);
    cudaGetSymbolAddress((void**)&pVT, g_VT);
    cudaGetSymbolAddress((void**)&pKV, g_KV);
    cudaGetSymbolAddress((void**)&pT,  g_T);

    // Phase A: per-(b,l) precomputes + block transform of all 51200 tokens
    prep_k<<<NBL, DM>>>(v_all, tv_all, amw1, amb1, wq);
    gemm128<<<dim3(NTOK/128, DH/128), 256>>>(emb, w1, pH, KD, DH, itxt, b1, nullptr, 1); // H = relu
    gemm128<<<dim3(NTOK/128, DM/128), 256>>>(pH, w2, pY, DH, DM, nullptr, b2, nullptr, 0); // Y
    ln_k<<<NTOK, DM>>>(gam, bet);                                                          // VT
    gemm128<<<dim3(NTOK/128, DM/128), 256>>>(pVT, wk, pKV, DM, DM, nullptr, nullptr, nullptr, 0);        // KV
    gemm128<<<dim3(NTOK/128, DM/128), 256>>>(pVT, amw1 + DM*DM, pH, DM, DM, nullptr, nullptr, pT, 2);    // tanh acts
    score_k<<<NTOK/8, 256>>>(amw2);

    // Phase B: selection ordering + sequential memory recurrence
    select_k<<<NBL, 64>>>(mtxt);
    recur_k<<<BSZ, 256>>>(itxt, mtxt, lens);

    // Phase C: pooling + head + output flatten
    final_k<<<BSZ, DM>>>(tv_all, itxt, lens);
    out_k<<<1, 256>>>(ow, ob, out, out_size);
}

// round 3
// speedup vs baseline: 1.3480x; 1.3480x over previous
#include <cuda_runtime.h>
#include <math.h>

// ---------------------------------------------------------------------------
// Problem constants
// ---------------------------------------------------------------------------
#define BSZ   16
#define LSEQ  50
#define NBLK  64
#define DM    256
#define DH    512
#define KD    768
#define NVOC  65536
#define NTOK  (BSZ*LSEQ*NBLK)   // 51200
#define NBL   (BSZ*LSEQ)        // 800
#define SLOTS (LSEQ*NBLK)       // 3200 per batch

__device__ __forceinline__ float neg_inf() { return __int_as_float(0xff800000); }

// ---------------------------------------------------------------------------
// Scratch (static device globals; no allocation)
// ---------------------------------------------------------------------------
__device__ __align__(128) float g_H [(size_t)NVOC*DH];  // relu hidden (per unique id)
__device__ __align__(128) float g_VT[(size_t)NVOC*DM];  // v_text (post-LN, per unique id)
__device__ __align__(128) float g_KV[(size_t)NVOC*DM];  // v_text @ wk (per unique id)
__device__ __align__(128) float g_S2[(size_t)NVOC*DM];  // v_text @ am_w1[D:] (per unique id)
__device__ __align__(128) float g_S [NTOK];             // raw attention scores (per token)
__device__ __align__(128) float g_T [NBL*DM];           // tv @ am_w1[:D] + am_b1
__device__ __align__(128) float g_QW[NBL*DM];           // (tv+v) @ wq
__device__ int   g_present[NVOC];
__device__ int   g_cidx[NVOC];                          // id -> compact index
__device__ int   g_ulist[NVOC];                         // compact index -> id (0-padded)
__device__ int   g_bsum[64];
__device__ int   g_boff[64];
__device__ int   g_ucnt[1];
__device__ int   g_tokc[NTOK];                          // token -> compact index
__device__ int   g_selslot[NTOK];
__device__ int   g_fslot[BSZ*64];
__device__ int   g_fid  [BSZ*64];
__device__ __align__(128) float g_vfin[BSZ*DM];
__device__ __align__(128) float g_mfin[BSZ*DM];

// ---------------------------------------------------------------------------
// Dedup pipeline: presence bitmap -> exclusive scan -> compact list
// ---------------------------------------------------------------------------
__global__ void zero_k()
{
    int i = blockIdx.x * blockDim.x + threadIdx.x;   // 512*256 = 131072 threads
    if (i < NVOC) { g_present[i] = 0; g_ulist[i] = 0; }
}

__global__ void mark_k(const int* __restrict__ ids)
{
    int t = blockIdx.x * blockDim.x + threadIdx.x;
    if (t < NTOK) g_present[ids[t]] = 1;
}

__global__ void scan1_k()   // 64 blocks x 1024: block-local exclusive scan
{
    __shared__ int s[1024];
    int t = threadIdx.x, g = blockIdx.x * 1024 + t;
    int p = g_present[g];
    s[t] = p; __syncthreads();
    for (int off = 1; off < 1024; off <<= 1) {
        int v = (t >= off) ? s[t - off] : 0;
        __syncthreads();
        s[t] += v;
        __syncthreads();
    }
    g_cidx[g] = s[t] - p;                 // exclusive, pre-offset
    if (t == 1023) g_bsum[blockIdx.x] = s[t];
}

__global__ void scan2_k()
{
    if (threadIdx.x == 0) {
        int run = 0;
        for (int i = 0; i < 64; i++) { g_boff[i] = run; run += g_bsum[i]; }
        g_ucnt[0] = run;
    }
}

__global__ void scan3_k()
{
    int t = threadIdx.x, g = blockIdx.x * 1024 + t;
    int c = g_cidx[g] + g_boff[blockIdx.x];
    g_cidx[g] = c;
    if (g_present[g]) g_ulist[c] = g;
}

__global__ void tokc_k(const int* __restrict__ ids)
{
    int t = blockIdx.x * blockDim.x + threadIdx.x;
    if (t < NTOK) g_tokc[t] = g_cidx[ids[t]];
}

// ---------------------------------------------------------------------------
// Double-buffered fp32 tiled GEMM: C[M,N] = act(A[M,K] @ B[K,N] + bias)
// BM=BN=128, BK=16, 256 threads, 8x8 microtile. Optional row gather on A.
// Early-exits blocks beyond *ucntp rows (rows are unique ids).
// Fixed k-ascending accumulation => deterministic per gathered row.
// ---------------------------------------------------------------------------
__global__ void __launch_bounds__(256) gemm_db(
    const float* __restrict__ A, const float* __restrict__ B, float* __restrict__ C,
    int Kdim, int Ndim,
    const int*  __restrict__ gather,
    const float* __restrict__ bias,
    int act,                              // 0=none 1=relu
    const int*  __restrict__ ucntp)
{
    __shared__ __align__(16) float As[2][16][128];
    __shared__ __align__(16) float Bs[2][16][128];
    const int bm = blockIdx.x * 128, bn = blockIdx.y * 128;
    if (bm >= ucntp[0]) return;
    const int tid = threadIdx.x;
    const int ty = tid >> 4, tx = tid & 15;
    const int arow = tid >> 2, akc = (tid & 3) * 4;
    const int bkr  = tid >> 5, bnc = (tid & 31) * 4;

    int r0 = bm + arow, r1 = bm + arow + 64;
    if (gather) { r0 = gather[r0]; r1 = gather[r1]; }
    const float* Ar0 = A + (size_t)r0 * Kdim + akc;
    const float* Ar1 = A + (size_t)r1 * Kdim + akc;
    const float* Bp  = B + (size_t)bkr * Ndim + bn + bnc;

    float acc[8][8];
#pragma unroll
    for (int i = 0; i < 8; i++)
#pragma unroll
        for (int j = 0; j < 8; j++) acc[i][j] = 0.f;

    const int steps = Kdim >> 4;
    // prologue: tile 0 -> buffer 0
    {
        float4 a0 = *(const float4*)(Ar0);
        float4 a1 = *(const float4*)(Ar1);
        float4 b0 = *(const float4*)(Bp);
        float4 b1 = *(const float4*)(Bp + (size_t)8 * Ndim);
        As[0][akc+0][arow] = a0.x; As[0][akc+1][arow] = a0.y;
        As[0][akc+2][arow] = a0.z; As[0][akc+3][arow] = a0.w;
        As[0][akc+0][arow+64] = a1.x; As[0][akc+1][arow+64] = a1.y;
        As[0][akc+2][arow+64] = a1.z; As[0][akc+3][arow+64] = a1.w;
        *(float4*)&Bs[0][bkr  ][bnc] = b0;
        *(float4*)&Bs[0][bkr+8][bnc] = b1;
    }
    __syncthreads();

    for (int s = 0; s < steps; s++) {
        const int cur = s & 1, nxt = cur ^ 1;
        float4 a0, a1, b0, b1;
        const bool more = (s + 1 < steps);
        if (more) {
            int k0 = (s + 1) << 4;
            a0 = *(const float4*)(Ar0 + k0);
            a1 = *(const float4*)(Ar1 + k0);
            b0 = *(const float4*)(Bp + (size_t)k0 * Ndim);
            b1 = *(const float4*)(Bp + (size_t)(k0 + 8) * Ndim);
        }
#pragma unroll
        for (int kk = 0; kk < 16; kk++) {
            float4 aA = *(const float4*)&As[cur][kk][ty*8];
            float4 aB = *(const float4*)&As[cur][kk][ty*8+4];
            float4 bA = *(const float4*)&Bs[cur][kk][tx*8];
            float4 bB = *(const float4*)&Bs[cur][kk][tx*8+4];
            float av[8] = {aA.x,aA.y,aA.z,aA.w,aB.x,aB.y,aB.z,aB.w};
            float bv[8] = {bA.x,bA.y,bA.z,bA.w,bB.x,bB.y,bB.z,bB.w};
#pragma unroll
            for (int i = 0; i < 8; i++)
#pragma unroll
                for (int j = 0; j < 8; j++)
                    acc[i][j] = fmaf(av[i], bv[j], acc[i][j]);
        }
        if (more) {
            As[nxt][akc+0][arow] = a0.x; As[nxt][akc+1][arow] = a0.y;
            As[nxt][akc+2][arow] = a0.z; As[nxt][akc+3][arow] = a0.w;
            As[nxt][akc+0][arow+64] = a1.x; As[nxt][akc+1][arow+64] = a1.y;
            As[nxt][akc+2][arow+64] = a1.z; As[nxt][akc+3][arow+64] = a1.w;
            *(float4*)&Bs[nxt][bkr  ][bnc] = b0;
            *(float4*)&Bs[nxt][bkr+8][bnc] = b1;
        }
        __syncthreads();
    }

#pragma unroll
    for (int i = 0; i < 8; i++) {
        int m = bm + ty*8 + i;
#pragma unroll
        for (int j = 0; j < 8; j++) {
            int n = bn + tx*8 + j;
            float v = acc[i][j];
            if (bias) v += bias[n];
            if (act == 1) v = fmaxf(v, 0.f);
            C[(size_t)m * Ndim + n] = v;
        }
    }
}

// ---------------------------------------------------------------------------
// GEMM2 + fused LayerNorm: VT = LN(H @ w2 + b2) over full rows.
// BM=128, BN=256 (full width), 512 threads, 8x8 microtile.
// ---------------------------------------------------------------------------
__global__ void __launch_bounds__(512) gemm_ln(
    const float* __restrict__ A, const float* __restrict__ B, float* __restrict__ C,
    const float* __restrict__ bias, const float* __restrict__ gamma,
    const float* __restrict__ beta, const int* __restrict__ ucntp)
{
    __shared__ __align__(16) float sbuf[16*128 + 16*256];   // As | Bs, reused as red
    __shared__ float mus[128], sis[128];
    float* As_ = sbuf;                 // [16][128]
    float* Bs_ = sbuf + 16*128;        // [16][256]
    const int bm = blockIdx.x * 128;
    if (bm >= ucntp[0]) return;
    const int tid = threadIdx.x;
    const int ty = tid >> 5, tx = tid & 31;          // 16 x 32
    const int arow = tid >> 2, akc = (tid & 3) * 4;  // 128 rows, one float4 each
    const int bkr  = tid >> 6, bnc = (tid & 63) * 4; // 8 k-rows x 2, 256 cols

    const float* Ar = A + (size_t)(bm + arow) * DH + akc;
    const float* Bp = B + (size_t)bkr * DM + bnc;

    float acc[8][8];
#pragma unroll
    for (int i = 0; i < 8; i++)
#pragma unroll
        for (int j = 0; j < 8; j++) acc[i][j] = 0.f;

    for (int k0 = 0; k0 < DH; k0 += 16) {
        float4 a0 = *(const float4*)(Ar + k0);
        float4 b0 = *(const float4*)(Bp + (size_t)k0 * DM);
        float4 b1 = *(const float4*)(Bp + (size_t)(k0 + 8) * DM);
        __syncthreads();
        As_[(akc+0)*128 + arow] = a0.x; As_[(akc+1)*128 + arow] = a0.y;
        As_[(akc+2)*128 + arow] = a0.z; As_[(akc+3)*128 + arow] = a0.w;
        *(float4*)&Bs_[ bkr     *256 + bnc] = b0;
        *(float4*)&Bs_[(bkr+8)  *256 + bnc] = b1;
        __syncthreads();
#pragma unroll
        for (int kk = 0; kk < 16; kk++) {
            float4 aA = *(const float4*)&As_[kk*128 + ty*8];
            float4 aB = *(const float4*)&As_[kk*128 + ty*8+4];
            float4 bA = *(const float4*)&Bs_[kk*256 + tx*8];
            float4 bB = *(const float4*)&Bs_[kk*256 + tx*8+4];
            float av[8] = {aA.x,aA.y,aA.z,aA.w,aB.x,aB.y,aB.z,aB.w};
            float bv[8] = {bA.x,bA.y,bA.z,bA.w,bB.x,bB.y,bB.z,bB.w};
#pragma unroll
            for (int i = 0; i < 8; i++)
#pragma unroll
                for (int j = 0; j < 8; j++)
                    acc[i][j] = fmaf(av[i], bv[j], acc[i][j]);
        }
    }
    __syncthreads();                    // done with As/Bs; reuse sbuf as red

    float* red = sbuf;                  // [128][33]
    // add bias, accumulate row partial sums (fixed j-ascending order)
#pragma unroll
    for (int i = 0; i < 8; i++) {
        float p = 0.f;
#pragma unroll
        for (int j = 0; j < 8; j++) {
            acc[i][j] += bias[tx*8 + j];
            p += acc[i][j];
        }
        red[(ty*8 + i)*33 + tx] = p;
    }
    __syncthreads();
    if (tid < 128) {
        float mu = 0.f;
        for (int t = 0; t < 32; t++) mu += red[tid*33 + t];
        mus[tid] = mu * (1.f/DM);
    }
    __syncthreads();
#pragma unroll
    for (int i = 0; i < 8; i++) {
        float mu = mus[ty*8 + i], p = 0.f;
#pragma unroll
        for (int j = 0; j < 8; j++) { float c = acc[i][j] - mu; p += c*c; }
        red[(ty*8 + i)*33 + tx] = p;
    }
    __syncthreads();
    if (tid < 128) {
        float v = 0.f;
        for (int t = 0; t < 32; t++) v += red[tid*33 + t];
        sis[tid] = rsqrtf(v * (1.f/DM) + 1e-5f);
    }
    __syncthreads();
#pragma unroll
    for (int i = 0; i < 8; i++) {
        int m = bm + ty*8 + i;
        float mu = mus[ty*8 + i], is = sis[ty*8 + i];
#pragma unroll
        for (int j = 0; j < 8; j++) {
            int n = tx*8 + j;
            C[(size_t)m * DM + n] = gamma[n] * (acc[i][j] - mu) * is + beta[n];
        }
    }
}

// ---------------------------------------------------------------------------
// Per-(b,l) precompute: g_T = tv @ am_w1[:D] + am_b1 ;  g_QW = (tv+v) @ wq
// ---------------------------------------------------------------------------
__global__ void prep_k(const float* __restrict__ v, const float* __restrict__ tv,
                       const float* __restrict__ am_w1, const float* __restrict__ am_b1,
                       const float* __restrict__ wq)
{
    __shared__ float tvs[DM];
    __shared__ float qs[DM];
    int bl = blockIdx.x, d = threadIdx.x;
    float t0 = tv[(size_t)bl*DM + d];
    tvs[d] = t0;
    qs[d]  = t0 + v[(size_t)bl*DM + d];
    __syncthreads();
    float t = am_b1[d], q = 0.f;
    for (int k = 0; k < DM; k++) {
        t = fmaf(tvs[k], am_w1[k*DM + d], t);
        q = fmaf(qs[k],  wq  [k*DM + d], q);
    }
    g_T [(size_t)bl*DM + d] = t;
    g_QW[(size_t)bl*DM + d] = q;
}

// ---------------------------------------------------------------------------
// Per-token score: score = sum_d tanh(S2[cidx,d] + T[bl,d]) * am_w2[d]
// One warp per token; fixed lane-strided order => bitwise-equal for equal
// (cidx, bl) pairs (duplicate ids within a visit).
// ---------------------------------------------------------------------------
__global__ void score2_k(const float* __restrict__ am_w2)
{
    int tok  = blockIdx.x * 8 + (threadIdx.x >> 5);
    int lane = threadIdx.x & 31;
    int c  = g_tokc[tok];
    int bl = tok >> 6;
    const float* s2 = g_S2 + (size_t)c * DM;
    const float* tt = g_T  + (size_t)bl * DM;
    float s = 0.f;
#pragma unroll
    for (int d = lane; d < DM; d += 32)
        s = fmaf(tanhf(s2[d] + tt[d]), am_w2[d], s);
    for (int o = 16; o > 0; o >>= 1) s += __shfl_down_sync(0xffffffffu, s, o);
    if (lane == 0) g_S[tok] = s;
}

// ---------------------------------------------------------------------------
// Per-visit stable sort (softmax->mask->top_k(64 of 64) equivalent)
// ---------------------------------------------------------------------------
__global__ void select_k(const int* __restrict__ masks)
{
    int bl = blockIdx.x, j = threadIdx.x;
    __shared__ float key[64];
    int tok = bl*64 + j;
    float k_ = masks[tok] ? g_S[tok] : neg_inf();
    key[j] = k_; __syncthreads();
    int rank = 0;
    for (int m = 0; m < 64; m++) {
        float o = key[m];
        rank += (o > k_) || (o == k_ && m < j);
    }
    g_selslot[bl*64 + rank] = (bl % LSEQ) * NBLK + j;
}

// ---------------------------------------------------------------------------
// Sequential memory recurrence: one block per batch, 49 steps.
// kvec rows gathered by compact id => duplicate ids bitwise identical.
// ---------------------------------------------------------------------------
__global__ void recur_k(const int* __restrict__ ids, const int* __restrict__ masks,
                        const int* __restrict__ lens)
{
    int b = blockIdx.x, tid = threadIdx.x;
    __shared__ __align__(16) float qw[DM];
    __shared__ int cslot[64], cmask[64];
    __shared__ int nslot[64], nmask[64];
    __shared__ int dslot[128], dmask[128], dcid[128];
    __shared__ float ev[128];

    if (tid < 64) {
        int slot = g_selslot[(b*LSEQ + 0)*64 + tid];
        cslot[tid] = slot;
        cmask[tid] = masks[b*SLOTS + slot];
    }
    int lb = lens[b];
    __syncthreads();

    for (int t = 1; t < LSEQ; t++) {
        qw[tid] = g_QW[(size_t)(b*LSEQ + t)*DM + tid];
        if (tid < 128) {
            int slot = (tid < 64) ? cslot[tid] : g_selslot[(b*LSEQ + t)*64 + (tid - 64)];
            dslot[tid] = slot;
            dmask[tid] = (tid < 64) ? cmask[tid] : masks[b*SLOTS + slot];
            dcid [tid] = g_tokc[b*SLOTS + slot];
        }
        __syncthreads();

        int w = tid >> 5, lane = tid & 31;
        for (int c = w; c < 128; c += 8) {
            const float4* kv = (const float4*)(g_KV + (size_t)dcid[c] * DM);
            const float4* q4 = (const float4*)qw;
            float4 k0 = kv[lane*2], k1 = kv[lane*2 + 1];
            float4 q0 = q4[lane*2], q1 = q4[lane*2 + 1];
            float s = k0.x*q0.x + k0.y*q0.y + k0.z*q0.z + k0.w*q0.w
                    + k1.x*q1.x + k1.y*q1.y + k1.z*q1.z + k1.w*q1.w;
            for (int o = 16; o > 0; o >>= 1) s += __shfl_down_sync(0xffffffffu, s, o);
            if (lane == 0) ev[c] = s;
        }
        __syncthreads();

        if (tid < 128) {
            float k_ = dmask[tid] ? ev[tid] : neg_inf();
            int rank = 0;
            for (int m = 0; m < 128; m++) {
                float o = dmask[m] ? ev[m] : neg_inf();
                rank += (o > k_) || (o == k_ && m < tid);
            }
            if (rank < 64) { nslot[rank] = dslot[tid]; nmask[rank] = dmask[tid]; }
        }
        __syncthreads();
        if (tid < 64) {
            cslot[tid] = nslot[tid];
            cmask[tid] = nmask[tid];
            if (t == lb - 1) g_fslot[b*64 + tid] = nslot[tid];
        }
        __syncthreads();
    }
}

// ---------------------------------------------------------------------------
// Pools
// ---------------------------------------------------------------------------
__global__ void final_k(const float* __restrict__ tv, const int* __restrict__ ids,
                        const int* __restrict__ lens)
{
    int b = blockIdx.x, d = threadIdx.x;
    int lb = lens[b];
    float mx = neg_inf();
    for (int l = 0; l < lb; l++) mx = fmaxf(mx, tv[((size_t)b*LSEQ + l)*DM + d]);
    g_vfin[b*DM + d] = mx;
    float mv = neg_inf();
    for (int m = 0; m < 64; m++) {
        int c = g_tokc[b*SLOTS + g_fslot[b*64 + m]];
        mv = fmaxf(mv, g_VT[(size_t)c*DM + d]);
    }
    g_mfin[b*DM + d] = mv;
    if (d < 64) g_fid[b*64 + d] = ids[b*SLOTS + g_fslot[b*64 + d]];
}

// ---------------------------------------------------------------------------
// Output head + flatten
// ---------------------------------------------------------------------------
__global__ void out_k(const float* __restrict__ ow, const float* __restrict__ ob,
                      float* __restrict__ out, int out_size)
{
    int tid = threadIdx.x;
    if (tid < 32) {
        int b = tid >> 1, o = tid & 1;
        float v = ob[o];
        for (int d = 0; d < DM; d++) v = fmaf(g_vfin[b*DM + d], ow[d*2 + o], v);
        for (int d = 0; d < DM; d++) v = fmaf(g_mfin[b*DM + d], ow[(DM + d)*2 + o], v);
        if (tid < out_size) out[tid] = v;
    }
    for (int i = tid; i < BSZ*64; i += blockDim.x)
        if (32 + i < out_size) out[32 + i] = (float)g_fid[i];
    for (int i = 32 + BSZ*64 + tid; i < out_size; i += blockDim.x)
        out[i] = 0.f;
}

// ---------------------------------------------------------------------------
// Launch
// ---------------------------------------------------------------------------
extern "C" void kernel_launch(void* const* d_in, const int* in_sizes, int n_in,
                              void* d_out, int out_size)
{
    const float* v_all  = (const float*)d_in[0];
    const float* tv_all = (const float*)d_in[1];
    const float* emb    = (const float*)d_in[2];
    const float* w1     = (const float*)d_in[3];
    const float* b1     = (const float*)d_in[4];
    const float* w2     = (const float*)d_in[5];
    const float* b2     = (const float*)d_in[6];
    const float* gam    = (const float*)d_in[7];
    const float* bet    = (const float*)d_in[8];
    const float* wq     = (const float*)d_in[9];
    const float* wk     = (const float*)d_in[10];
    const float* amw1   = (const float*)d_in[11];
    const float* amb1   = (const float*)d_in[12];
    const float* amw2   = (const float*)d_in[13];
    const float* ow     = (const float*)d_in[14];
    const float* ob     = (const float*)d_in[15];
    const int*   itxt   = (const int*)d_in[16];
    const int*   mtxt   = (const int*)d_in[17];
    const int*   lens   = (const int*)d_in[18];
    float* out = (float*)d_out;

    float *pH, *pVT, *pKV, *pS2;
    int *pU, *pUL;
    cudaGetSymbolAddress((void**)&pH,  g_H);
    cudaGetSymbolAddress((void**)&pVT, g_VT);
    cudaGetSymbolAddress((void**)&pKV, g_KV);
    cudaGetSymbolAddress((void**)&pS2, g_S2);
    cudaGetSymbolAddress((void**)&pU,  g_ucnt);
    cudaGetSymbolAddress((void**)&pUL, g_ulist);

    // Dedup pipeline
    zero_k<<<512, 256>>>();
    mark_k<<<NTOK/256, 256>>>(itxt);
    scan1_k<<<64, 1024>>>();
    scan2_k<<<1, 64>>>();
    scan3_k<<<64, 1024>>>();
    tokc_k<<<NTOK/256, 256>>>(itxt);

    // Per-(b,l) precomputes
    prep_k<<<NBL, DM>>>(v_all, tv_all, amw1, amb1, wq);

    // Per-unique-id heavy math (grid covers vocab; blocks early-exit past ucnt)
    gemm_db<<<dim3(NVOC/128, DH/128), 256>>>(emb, w1, pH, KD, DH, pUL, b1, 1, pU);
    gemm_ln<<<NVOC/128, 512>>>(pH, w2, pVT, b2, gam, bet, pU);
    gemm_db<<<dim3(NVOC/128, DM/128), 256>>>(pVT, wk, pKV, DM, DM, nullptr, nullptr, 0, pU);
    gemm_db<<<dim3(NVOC/128, DM/128), 256>>>(pVT, amw1 + DM*DM, pS2, DM, DM, nullptr, nullptr, 0, pU);

    // Per-token score + selection + recurrence
    score2_k<<<NTOK/8, 256>>>(amw2);
    select_k<<<NBL, 64>>>(mtxt);
    recur_k<<<BSZ, 256>>>(itxt, mtxt, lens);

    // Pooling + head
    final_k<<<BSZ, DM>>>(tv_all, itxt, lens);
    out_k<<<1, 256>>>(ow, ob, out, out_size);
}

// round 4
// speedup vs baseline: 1.6003x; 1.1872x over previous
#include <cuda_runtime.h>
#include <math.h>
#include <stdint.h>

// ---------------------------------------------------------------------------
// Problem constants
// ---------------------------------------------------------------------------
#define BSZ   16
#define LSEQ  50
#define NBLK  64
#define DM    256
#define DH    512
#define KD    768
#define NVOC  65536
#define NTOK  (BSZ*LSEQ*NBLK)   // 51200
#define NBL   (BSZ*LSEQ)        // 800
#define SLOTS (LSEQ*NBLK)       // 3200 per batch

__device__ __forceinline__ float neg_inf() { return __int_as_float(0xff800000); }

// ---------------------------------------------------------------------------
// Scratch (static device globals; no allocation)
// ---------------------------------------------------------------------------
__device__ __align__(128) float g_H [(size_t)NVOC*DH];  // relu hidden (per unique id)
__device__ __align__(128) float g_Y [(size_t)NVOC*DM];  // pre-LN (per unique id)
__device__ __align__(128) float g_VT[(size_t)NVOC*DM];  // v_text post-LN (per unique id)
__device__ __align__(128) float g_KV[(size_t)NVOC*DM];  // v_text @ wk
__device__ __align__(128) float g_S2[(size_t)NVOC*DM];  // v_text @ am_w1[D:]
__device__ __align__(128) float g_S [NTOK];             // raw attention scores
__device__ __align__(128) float g_T [NBL*DM];           // tv @ am_w1[:D] + am_b1
__device__ __align__(128) float g_QW[NBL*DM];           // (tv+v) @ wq
__device__ int   g_present[NVOC];
__device__ int   g_cidx[NVOC];
__device__ int   g_ulist[NVOC];
__device__ int   g_bsum[64];
__device__ int   g_boff[64];
__device__ int   g_ucnt[1];
__device__ int   g_tokc[NTOK];
__device__ int   g_selslot[NTOK];
__device__ int   g_fslot[BSZ*64];
__device__ int   g_fid  [BSZ*64];
__device__ __align__(128) float g_vfin[BSZ*DM];
__device__ __align__(128) float g_mfin[BSZ*DM];

// ---------------------------------------------------------------------------
// Dedup pipeline
// ---------------------------------------------------------------------------
__global__ void zero_k()
{
    int i = blockIdx.x * blockDim.x + threadIdx.x;
    if (i < NVOC) { g_present[i] = 0; g_ulist[i] = 0; }
}
__global__ void mark_k(const int* __restrict__ ids)
{
    int t = blockIdx.x * blockDim.x + threadIdx.x;
    if (t < NTOK) g_present[ids[t]] = 1;
}
__global__ void scan1_k()
{
    __shared__ int s[1024];
    int t = threadIdx.x, g = blockIdx.x * 1024 + t;
    int p = g_present[g];
    s[t] = p; __syncthreads();
    for (int off = 1; off < 1024; off <<= 1) {
        int v = (t >= off) ? s[t - off] : 0;
        __syncthreads();
        s[t] += v;
        __syncthreads();
    }
    g_cidx[g] = s[t] - p;
    if (t == 1023) g_bsum[blockIdx.x] = s[t];
}
__global__ void scan2_k()
{
    if (threadIdx.x == 0) {
        int run = 0;
        for (int i = 0; i < 64; i++) { g_boff[i] = run; run += g_bsum[i]; }
        g_ucnt[0] = run;
    }
}
__global__ void scan3_k()
{
    int t = threadIdx.x, g = blockIdx.x * 1024 + t;
    int c = g_cidx[g] + g_boff[blockIdx.x];
    g_cidx[g] = c;
    if (g_present[g]) g_ulist[c] = g;
}
__global__ void tokc_k(const int* __restrict__ ids)
{
    int t = blockIdx.x * blockDim.x + threadIdx.x;
    if (t < NTOK) g_tokc[t] = g_cidx[ids[t]];
}

// ---------------------------------------------------------------------------
// TF32 split helpers
// ---------------------------------------------------------------------------
__device__ __forceinline__ uint32_t f2tf(float x)
{
    uint32_t r;
    asm("cvt.rna.tf32.f32 %0, %1;" : "=r"(r) : "f"(x));
    return r;
}
__device__ __forceinline__ void split_tf(float x, float& hi, float& lo)
{
    uint32_t h = f2tf(x);
    hi = __uint_as_float(h);
    lo = __uint_as_float(f2tf(x - hi));
}
__device__ __forceinline__ void mma_tf32(float c[4], const uint32_t a[4], const uint32_t b[2])
{
    asm volatile(
        "mma.sync.aligned.m16n8k8.row.col.f32.tf32.tf32.f32 "
        "{%0,%1,%2,%3}, {%4,%5,%6,%7}, {%8,%9}, {%0,%1,%2,%3};"
        : "+f"(c[0]), "+f"(c[1]), "+f"(c[2]), "+f"(c[3])
        : "r"(a[0]), "r"(a[1]), "r"(a[2]), "r"(a[3]), "r"(b[0]), "r"(b[1]));
}

// ---------------------------------------------------------------------------
// Tensor-core GEMM, 2-term TF32 split (3 passes, fp32-comparable accuracy).
// C[M,N] = act(A[M,K] @ B[K,N] + bias).  BM=128, BN=128, BK=32.
// 256 threads = 8 warps (4m x 2n), warp tile 32x64 = 2x8 m16n8k8 tiles.
// smem holds pre-split hi/lo planes; conflict-free strides (A:36, B:136).
// Optional A-row gather (unique-id list); early-exit past ucnt rows.
// Fixed accumulation order => deterministic per gathered row.
// ---------------------------------------------------------------------------
#define A_STR 36
#define B_STR 136
#define A_TILE (128*A_STR)   // 4608 floats
#define B_TILE (32*B_STR)    // 4352 floats
#define BUF_FLTS (2*A_TILE + 2*B_TILE)   // Ah,Al,Bh,Bl = 17920
#define GEMM_SMEM (2*BUF_FLTS*4)         // 143360 bytes

__global__ void __launch_bounds__(256, 1) gemm_tc(
    const float* __restrict__ A, const float* __restrict__ B, float* __restrict__ C,
    int Kdim, int Ndim,
    const int*  __restrict__ gather,
    const float* __restrict__ bias,
    int act,                               // 0=none 1=relu
    const int*  __restrict__ ucntp)
{
    extern __shared__ float sm[];
    const int bm = blockIdx.x * 128, bn = blockIdx.y * 128;
    if (bm >= ucntp[0]) return;
    const int tid  = threadIdx.x;
    const int wid  = tid >> 5, lane = tid & 31;
    const int wm   = (wid >> 1) * 32;      // warp m offset in tile
    const int wn   = (wid & 1) * 64;       // warp n offset in tile
    const int grp  = lane >> 2, qd = lane & 3;

    // fill mapping
    const int a_row  = tid >> 1;           // 0..127
    const int a_colh = (tid & 1) * 16;     // 0 or 16
    const int b_row  = tid >> 3;           // 0..31
    const int b_colg = (tid & 7) * 16;     // 0..112

    int ar = bm + a_row;
    if (gather) ar = gather[ar];
    const float* Ap = A + (size_t)ar * Kdim + a_colh;
    const float* Bp = B + (size_t)b_row * Ndim + bn + b_colg;

    float acc[2][8][4];
#pragma unroll
    for (int mi = 0; mi < 2; mi++)
#pragma unroll
        for (int ni = 0; ni < 8; ni++)
#pragma unroll
            for (int j = 0; j < 4; j++) acc[mi][ni][j] = 0.f;

    const int ktiles = Kdim >> 5;

    // fill one buffer from register-staged float4s
    auto stage = [&](float* buf, const float4* av, const float4* bv) {
        float* Ah = buf;
        float* Al = buf + A_TILE;
        float* Bh = buf + 2*A_TILE;
        float* Bl = buf + 2*A_TILE + B_TILE;
#pragma unroll
        for (int j = 0; j < 4; j++) {
            float4 v = av[j];
            float4 h4, l4;
            split_tf(v.x, h4.x, l4.x); split_tf(v.y, h4.y, l4.y);
            split_tf(v.z, h4.z, l4.z); split_tf(v.w, h4.w, l4.w);
            *(float4*)&Ah[a_row*A_STR + a_colh + j*4] = h4;
            *(float4*)&Al[a_row*A_STR + a_colh + j*4] = l4;
        }
#pragma unroll
        for (int j = 0; j < 4; j++) {
            float4 v = bv[j];
            float4 h4, l4;
            split_tf(v.x, h4.x, l4.x); split_tf(v.y, h4.y, l4.y);
            split_tf(v.z, h4.z, l4.z); split_tf(v.w, h4.w, l4.w);
            *(float4*)&Bh[b_row*B_STR + b_colg + j*4] = h4;
            *(float4*)&Bl[b_row*B_STR + b_colg + j*4] = l4;
        }
    };

    // prologue: tile 0 -> buffer 0
    {
        float4 av[4], bv[4];
#pragma unroll
        for (int j = 0; j < 4; j++) av[j] = *(const float4*)(Ap + j*4);
#pragma unroll
        for (int j = 0; j < 4; j++) bv[j] = *(const float4*)(Bp + j*4);
        stage(sm, av, bv);
    }
    __syncthreads();

    for (int kt = 0; kt < ktiles; kt++) {
        float* cur = sm + (kt & 1) * BUF_FLTS;
        float* nxt = sm + ((kt & 1) ^ 1) * BUF_FLTS;
        const bool more = (kt + 1 < ktiles);
        float4 av[4], bv[4];
        if (more) {
            const float* Ap2 = Ap + (kt + 1) * 32;
            const float* Bp2 = Bp + (size_t)(kt + 1) * 32 * Ndim;
#pragma unroll
            for (int j = 0; j < 4; j++) av[j] = *(const float4*)(Ap2 + j*4);
#pragma unroll
            for (int j = 0; j < 4; j++) bv[j] = *(const float4*)(Bp2 + j*4);
        }

        const float* Ah = cur;
        const float* Al = cur + A_TILE;
        const float* Bh = cur + 2*A_TILE;
        const float* Bl = cur + 2*A_TILE + B_TILE;

#pragma unroll
        for (int k8 = 0; k8 < 4; k8++) {
            const int c0 = k8*8 + qd, c1 = c0 + 4;
            uint32_t ah[2][4], al[2][4];
#pragma unroll
            for (int mi = 0; mi < 2; mi++) {
                const int r0 = wm + mi*16 + grp, r1 = r0 + 8;
                ah[mi][0] = __float_as_uint(Ah[r0*A_STR + c0]);
                ah[mi][1] = __float_as_uint(Ah[r1*A_STR + c0]);
                ah[mi][2] = __float_as_uint(Ah[r0*A_STR + c1]);
                ah[mi][3] = __float_as_uint(Ah[r1*A_STR + c1]);
                al[mi][0] = __float_as_uint(Al[r0*A_STR + c0]);
                al[mi][1] = __float_as_uint(Al[r1*A_STR + c0]);
                al[mi][2] = __float_as_uint(Al[r0*A_STR + c1]);
                al[mi][3] = __float_as_uint(Al[r1*A_STR + c1]);
            }
#pragma unroll
            for (int ni = 0; ni < 8; ni++) {
                const int n = wn + ni*8 + grp;
                uint32_t bh[2], bl2[2];
                bh[0]  = __float_as_uint(Bh[c0*B_STR + n]);
                bh[1]  = __float_as_uint(Bh[c1*B_STR + n]);
                bl2[0] = __float_as_uint(Bl[c0*B_STR + n]);
                bl2[1] = __float_as_uint(Bl[c1*B_STR + n]);
#pragma unroll
                for (int mi = 0; mi < 2; mi++) {
                    mma_tf32(acc[mi][ni], ah[mi], bh);
                    mma_tf32(acc[mi][ni], al[mi], bh);
                    mma_tf32(acc[mi][ni], ah[mi], bl2);
                }
            }
        }

        if (more) stage(nxt, av, bv);
        __syncthreads();
    }

    // epilogue
#pragma unroll
    for (int mi = 0; mi < 2; mi++) {
        const int r0 = bm + wm + mi*16 + grp;
#pragma unroll
        for (int ni = 0; ni < 8; ni++) {
            const int n = bn + wn + ni*8 + qd*2;
            float b0 = bias ? bias[n] : 0.f;
            float b1 = bias ? bias[n+1] : 0.f;
            float v0 = acc[mi][ni][0] + b0, v1 = acc[mi][ni][1] + b1;
            float v2 = acc[mi][ni][2] + b0, v3 = acc[mi][ni][3] + b1;
            if (act == 1) {
                v0 = fmaxf(v0, 0.f); v1 = fmaxf(v1, 0.f);
                v2 = fmaxf(v2, 0.f); v3 = fmaxf(v3, 0.f);
            }
            *(float2*)&C[(size_t)r0 * Ndim + n]       = make_float2(v0, v1);
            *(float2*)&C[(size_t)(r0+8) * Ndim + n]   = make_float2(v2, v3);
        }
    }
}

// ---------------------------------------------------------------------------
// LayerNorm: one warp per unique row, float4 loads, fixed shuffle tree.
// ---------------------------------------------------------------------------
__global__ void ln_k2(const float* __restrict__ gamma, const float* __restrict__ beta,
                      const int* __restrict__ ucntp)
{
    int row  = blockIdx.x * 8 + (threadIdx.x >> 5);
    int lane = threadIdx.x & 31;
    if (row >= ucntp[0]) return;
    const float4* y4 = (const float4*)(g_Y + (size_t)row * DM);
    float4 v0 = y4[lane], v1 = y4[lane + 32];
    float s = v0.x+v0.y+v0.z+v0.w + v1.x+v1.y+v1.z+v1.w;
    for (int o = 16; o > 0; o >>= 1) s += __shfl_xor_sync(0xffffffffu, s, o);
    float mu = s * (1.f/DM);
    float4 c0 = make_float4(v0.x-mu, v0.y-mu, v0.z-mu, v0.w-mu);
    float4 c1 = make_float4(v1.x-mu, v1.y-mu, v1.z-mu, v1.w-mu);
    float q = c0.x*c0.x+c0.y*c0.y+c0.z*c0.z+c0.w*c0.w
            + c1.x*c1.x+c1.y*c1.y+c1.z*c1.z+c1.w*c1.w;
    for (int o = 16; o > 0; o >>= 1) q += __shfl_xor_sync(0xffffffffu, q, o);
    float is = rsqrtf(q * (1.f/DM) + 1e-5f);
    const float4* g4 = (const float4*)gamma;
    const float4* b4 = (const float4*)beta;
    float4 ga = g4[lane], gb = g4[lane+32], ba = b4[lane], bb = b4[lane+32];
    float4 o0 = make_float4(ga.x*c0.x*is+ba.x, ga.y*c0.y*is+ba.y,
                            ga.z*c0.z*is+ba.z, ga.w*c0.w*is+ba.w);
    float4 o1 = make_float4(gb.x*c1.x*is+bb.x, gb.y*c1.y*is+bb.y,
                            gb.z*c1.z*is+bb.z, gb.w*c1.w*is+bb.w);
    float4* vt4 = (float4*)(g_VT + (size_t)row * DM);
    vt4[lane] = o0; vt4[lane + 32] = o1;
}

// ---------------------------------------------------------------------------
// Per-(b,l) precompute: g_T = tv @ am_w1[:D] + am_b1 ;  g_QW = (tv+v) @ wq
// ---------------------------------------------------------------------------
__global__ void prep_k(const float* __restrict__ v, const float* __restrict__ tv,
                       const float* __restrict__ am_w1, const float* __restrict__ am_b1,
                       const float* __restrict__ wq)
{
    __shared__ float tvs[DM];
    __shared__ float qs[DM];
    int bl = blockIdx.x, d = threadIdx.x;
    float t0 = tv[(size_t)bl*DM + d];
    tvs[d] = t0;
    qs[d]  = t0 + v[(size_t)bl*DM + d];
    __syncthreads();
    float t = am_b1[d], q = 0.f;
    for (int k = 0; k < DM; k++) {
        t = fmaf(tvs[k], am_w1[k*DM + d], t);
        q = fmaf(qs[k],  wq  [k*DM + d], q);
    }
    g_T [(size_t)bl*DM + d] = t;
    g_QW[(size_t)bl*DM + d] = q;
}

// ---------------------------------------------------------------------------
// Per-token score: sum_d tanh(S2[cidx,d] + T[bl,d]) * am_w2[d]
// ---------------------------------------------------------------------------
__global__ void score2_k(const float* __restrict__ am_w2)
{
    int tok  = blockIdx.x * 8 + (threadIdx.x >> 5);
    int lane = threadIdx.x & 31;
    int c  = g_tokc[tok];
    int bl = tok >> 6;
    const float* s2 = g_S2 + (size_t)c * DM;
    const float* tt = g_T  + (size_t)bl * DM;
    float s = 0.f;
#pragma unroll
    for (int d = lane; d < DM; d += 32)
        s = fmaf(tanhf(s2[d] + tt[d]), am_w2[d], s);
    for (int o = 16; o > 0; o >>= 1) s += __shfl_down_sync(0xffffffffu, s, o);
    if (lane == 0) g_S[tok] = s;
}

// ---------------------------------------------------------------------------
// Per-visit stable sort (softmax->mask->top_k(64 of 64) equivalent)
// ---------------------------------------------------------------------------
__global__ void select_k(const int* __restrict__ masks)
{
    int bl = blockIdx.x, j = threadIdx.x;
    __shared__ float key[64];
    int tok = bl*64 + j;
    float k_ = masks[tok] ? g_S[tok] : neg_inf();
    key[j] = k_; __syncthreads();
    int rank = 0;
    for (int m = 0; m < 64; m++) {
        float o = key[m];
        rank += (o > k_) || (o == k_ && m < j);
    }
    g_selslot[bl*64 + rank] = (bl % LSEQ) * NBLK + j;
}

// ---------------------------------------------------------------------------
// Sequential memory recurrence
// ---------------------------------------------------------------------------
__global__ void recur_k(const int* __restrict__ ids, const int* __restrict__ masks,
                        const int* __restrict__ lens)
{
    int b = blockIdx.x, tid = threadIdx.x;
    __shared__ __align__(16) float qw[DM];
    __shared__ int cslot[64], cmask[64];
    __shared__ int nslot[64], nmask[64];
    __shared__ int dslot[128], dmask[128], dcid[128];
    __shared__ float ev[128];

    if (tid < 64) {
        int slot = g_selslot[(b*LSEQ + 0)*64 + tid];
        cslot[tid] = slot;
        cmask[tid] = masks[b*SLOTS + slot];
    }
    int lb = lens[b];
    __syncthreads();

    for (int t = 1; t < LSEQ; t++) {
        qw[tid] = g_QW[(size_t)(b*LSEQ + t)*DM + tid];
        if (tid < 128) {
            int slot = (tid < 64) ? cslot[tid] : g_selslot[(b*LSEQ + t)*64 + (tid - 64)];
            dslot[tid] = slot;
            dmask[tid] = (tid < 64) ? cmask[tid] : masks[b*SLOTS + slot];
            dcid [tid] = g_tokc[b*SLOTS + slot];
        }
        __syncthreads();

        int w = tid >> 5, lane = tid & 31;
        for (int c = w; c < 128; c += 8) {
            const float4* kv = (const float4*)(g_KV + (size_t)dcid[c] * DM);
            const float4* q4 = (const float4*)qw;
            float4 k0 = kv[lane*2], k1 = kv[lane*2 + 1];
            float4 q0 = q4[lane*2], q1 = q4[lane*2 + 1];
            float s = k0.x*q0.x + k0.y*q0.y + k0.z*q0.z + k0.w*q0.w
                    + k1.x*q1.x + k1.y*q1.y + k1.z*q1.z + k1.w*q1.w;
            for (int o = 16; o > 0; o >>= 1) s += __shfl_down_sync(0xffffffffu, s, o);
            if (lane == 0) ev[c] = s;
        }
        __syncthreads();

        if (tid < 128) {
            float k_ = dmask[tid] ? ev[tid] : neg_inf();
            int rank = 0;
            for (int m = 0; m < 128; m++) {
                float o = dmask[m] ? ev[m] : neg_inf();
                rank += (o > k_) || (o == k_ && m < tid);
            }
            if (rank < 64) { nslot[rank] = dslot[tid]; nmask[rank] = dmask[tid]; }
        }
        __syncthreads();
        if (tid < 64) {
            cslot[tid] = nslot[tid];
            cmask[tid] = nmask[tid];
            if (t == lb - 1) g_fslot[b*64 + tid] = nslot[tid];
        }
        __syncthreads();
    }
}

// ---------------------------------------------------------------------------
// Pools
// ---------------------------------------------------------------------------
__global__ void final_k(const float* __restrict__ tv, const int* __restrict__ ids,
                        const int* __restrict__ lens)
{
    int b = blockIdx.x, d = threadIdx.x;
    int lb = lens[b];
    float mx = neg_inf();
    for (int l = 0; l < lb; l++) mx = fmaxf(mx, tv[((size_t)b*LSEQ + l)*DM + d]);
    g_vfin[b*DM + d] = mx;
    float mv = neg_inf();
    for (int m = 0; m < 64; m++) {
        int c = g_tokc[b*SLOTS + g_fslot[b*64 + m]];
        mv = fmaxf(mv, g_VT[(size_t)c*DM + d]);
    }
    g_mfin[b*DM + d] = mv;
    if (d < 64) g_fid[b*64 + d] = ids[b*SLOTS + g_fslot[b*64 + d]];
}

// ---------------------------------------------------------------------------
// Output head + flatten
// ---------------------------------------------------------------------------
__global__ void out_k(const float* __restrict__ ow, const float* __restrict__ ob,
                      float* __restrict__ out, int out_size)
{
    int tid = threadIdx.x;
    if (tid < 32) {
        int b = tid >> 1, o = tid & 1;
        float v = ob[o];
        for (int d = 0; d < DM; d++) v = fmaf(g_vfin[b*DM + d], ow[d*2 + o], v);
        for (int d = 0; d < DM; d++) v = fmaf(g_mfin[b*DM + d], ow[(DM + d)*2 + o], v);
        if (tid < out_size) out[tid] = v;
    }
    for (int i = tid; i < BSZ*64; i += blockDim.x)
        if (32 + i < out_size) out[32 + i] = (float)g_fid[i];
    for (int i = 32 + BSZ*64 + tid; i < out_size; i += blockDim.x)
        out[i] = 0.f;
}

// ---------------------------------------------------------------------------
// Launch
// ---------------------------------------------------------------------------
extern "C" void kernel_launch(void* const* d_in, const int* in_sizes, int n_in,
                              void* d_out, int out_size)
{
    const float* v_all  = (const float*)d_in[0];
    const float* tv_all = (const float*)d_in[1];
    const float* emb    = (const float*)d_in[2];
    const float* w1     = (const float*)d_in[3];
    const float* b1     = (const float*)d_in[4];
    const float* w2     = (const float*)d_in[5];
    const float* b2     = (const float*)d_in[6];
    const float* gam    = (const float*)d_in[7];
    const float* bet    = (const float*)d_in[8];
    const float* wq     = (const float*)d_in[9];
    const float* wk     = (const float*)d_in[10];
    const float* amw1   = (const float*)d_in[11];
    const float* amb1   = (const float*)d_in[12];
    const float* amw2   = (const float*)d_in[13];
    const float* ow     = (const float*)d_in[14];
    const float* ob     = (const float*)d_in[15];
    const int*   itxt   = (const int*)d_in[16];
    const int*   mtxt   = (const int*)d_in[17];
    const int*   lens   = (const int*)d_in[18];
    float* out = (float*)d_out;

    float *pH, *pY, *pVT, *pKV, *pS2;
    int *pU, *pUL;
    cudaGetSymbolAddress((void**)&pH,  g_H);
    cudaGetSymbolAddress((void**)&pY,  g_Y);
    cudaGetSymbolAddress((void**)&pVT, g_VT);
    cudaGetSymbolAddress((void**)&pKV, g_KV);
    cudaGetSymbolAddress((void**)&pS2, g_S2);
    cudaGetSymbolAddress((void**)&pU,  g_ucnt);
    cudaGetSymbolAddress((void**)&pUL, g_ulist);

    cudaFuncSetAttribute(gemm_tc, cudaFuncAttributeMaxDynamicSharedMemorySize, GEMM_SMEM);

    // Dedup pipeline
    zero_k<<<512, 256>>>();
    mark_k<<<NTOK/256, 256>>>(itxt);
    scan1_k<<<64, 1024>>>();
    scan2_k<<<1, 64>>>();
    scan3_k<<<64, 1024>>>();
    tokc_k<<<NTOK/256, 256>>>(itxt);

    // Per-(b,l) precomputes
    prep_k<<<NBL, DM>>>(v_all, tv_all, amw1, amb1, wq);

    // Per-unique-id heavy math on tensor cores (early exit past ucnt)
    gemm_tc<<<dim3(NVOC/128, DH/128), 256, GEMM_SMEM>>>(emb, w1, pH, KD, DH, pUL, b1, 1, pU);
    gemm_tc<<<dim3(NVOC/128, DM/128), 256, GEMM_SMEM>>>(pH, w2, pY, DH, DM, nullptr, b2, 0, pU);
    ln_k2<<<NVOC/8, 256>>>(gam, bet, pU);
    gemm_tc<<<dim3(NVOC/128, DM/128), 256, GEMM_SMEM>>>(pVT, wk, pKV, DM, DM, nullptr, nullptr, 0, pU);
    gemm_tc<<<dim3(NVOC/128, DM/128), 256, GEMM_SMEM>>>(pVT, amw1 + DM*DM, pS2, DM, DM, nullptr, nullptr, 0, pU);

    // Per-token score + selection + recurrence
    score2_k<<<NTOK/8, 256>>>(amw2);
    select_k<<<NBL, 64>>>(mtxt);
    recur_k<<<BSZ, 256>>>(itxt, mtxt, lens);

    // Pooling + head
    final_k<<<BSZ, DM>>>(tv_all, itxt, lens);
    out_k<<<1, 256>>>(ow, ob, out, out_size);
}